// round 14
// baseline (speedup 1.0000x reference)
#include <cuda_runtime.h>
#include <cuda_bf16.h>
#include <math.h>

// Problem shape (fixed by the dataset): x = [4, 32, 4096, 128] fp32.
#define SEQ     4096
#define HDIM    128
#define HALF    (HDIM / 2)          // 64 rotation pairs per row
#define F4_ROW  (HDIM / 4)          // 32 float4 per row (2 pairs per float4)
#define BH      (4 * 32)            // 128 batch*head slices
#define SLICE   (SEQ * F4_ROW)      // float4 per bh-slice = 131072
#define SPLIT   2                   // bh-loop split -> 2x threads, 2x MLP
#define BH_PER  (BH / SPLIT)        // 64 bh iterations per thread
#define BATCH   8                   // loads in flight per thread

// ---------------------------------------------------------------------------
// Position loader with dtype sniffing (reference says int64; harness may have
// materialized int32/float32). Positions are small non-negative ints.
// ---------------------------------------------------------------------------
__device__ __forceinline__ double load_pos(const void* p, int s) {
    const unsigned int* w = (const unsigned int*)p;
    bool hi_zero = (w[1] == 0u) & (w[3] == 0u) & (w[5] == 0u) & (w[7] == 0u);
    bool lo_some = (w[0] | w[2] | w[4] | w[6]) != 0u;
    if (hi_zero && (lo_some || (w[8] | w[9]) == 0u)) {
        return (double)((const long long*)p)[s];
    }
    bool small_ints = (w[1] < (1u << 24)) & (w[2] < (1u << 24)) &
                      (w[3] < (1u << 24));
    if (small_ints) return (double)((const int*)p)[s];
    return (double)((const float*)p)[s];
}

__device__ __forceinline__ float reduce_2pi(double a) {
    const double INV_2PI = 0.15915494309189535;
    const double TWO_PI  = 6.283185307179586;
    double k = rint(a * INV_2PI);
    return (float)(a - k * TWO_PI);
}

// ---------------------------------------------------------------------------
// Fused kernel, best-measured configuration (R7 skeleton):
//   SPLIT=2, BATCH=8 prefetch-before-trig, 256 threads/CTA.
// Micro-refinements: __ldg + plain stores (idiom of the best DRAM% run),
// and the second inv_freq comes from a constant-folded multiplier (one
// runtime exp2 per thread instead of two).
// ---------------------------------------------------------------------------
__global__ __launch_bounds__(256) void rope_fused(
    const float4* __restrict__ x, float4* __restrict__ out,
    const void* __restrict__ pos) {
    int t = blockIdx.x * blockDim.x + threadIdx.x;   // 0..SLICE-1
    int s = t >> 5;          // seq index
    int j = t & 31;          // float4 within row -> pairs 2j, 2j+1

    size_t off = (size_t)blockIdx.y * (size_t)BH_PER * SLICE + (size_t)t;

    // Prefetch batch 0 (independent of trig).
    float4 v[BATCH];
#pragma unroll
    for (int k = 0; k < BATCH; ++k)
        v[k] = __ldg(&x[off + (size_t)k * SLICE]);

    // Per-thread trig (hidden under the loads above). One runtime exp2:
    // f1/f0 ratio is a compile-time constant the compiler folds.
    double p = load_pos(pos, s);
    const double LOG2_THETA = 13.287712379549449;   // log2(10000)
    double f0 = exp2(-((double)(2 * j) / (double)HALF) * LOG2_THETA);
    double f1 = f0 * exp2(-(1.0 / (double)HALF) * LOG2_THETA); // const-folded
    float a0 = reduce_2pi(p * f0);
    float a1 = reduce_2pi(p * f1);
    float s0, c0, s1, c1;
    sincosf(a0, &s0, &c0);
    sincosf(a1, &s1, &c1);

#pragma unroll
    for (int bb = 0; bb < BH_PER / BATCH; ++bb) {
        // Rotate + store current batch.
#pragma unroll
        for (int k = 0; k < BATCH; ++k) {
            float4 r;
            r.x = c0 * v[k].x - s0 * v[k].y;
            r.y = s0 * v[k].x + c0 * v[k].y;
            r.z = c1 * v[k].z - s1 * v[k].w;
            r.w = s1 * v[k].z + c1 * v[k].w;
            out[off + (size_t)k * SLICE] = r;
        }
        off += (size_t)BATCH * SLICE;
        // Prefetch next batch.
        if (bb + 1 < BH_PER / BATCH) {
#pragma unroll
            for (int k = 0; k < BATCH; ++k)
                v[k] = __ldg(&x[off + (size_t)k * SLICE]);
        }
    }
}

// ---------------------------------------------------------------------------
// Entry point. Identify x vs token_positions by element count (robust to
// input ordering): x has 67108864 elements, positions 4096.
// ---------------------------------------------------------------------------
extern "C" void kernel_launch(void* const* d_in, const int* in_sizes, int n_in,
                              void* d_out, int out_size) {
    const void* xp = d_in[0];
    const void* pp = (n_in > 1) ? d_in[1] : d_in[0];
    if (n_in > 1 && in_sizes[0] < in_sizes[1]) {
        xp = d_in[1];
        pp = d_in[0];
    }
    const float4* x = (const float4*)xp;
    float4* out = (float4*)d_out;

    dim3 grid(SLICE / 256, SPLIT);
    rope_fused<<<grid, 256>>>(x, out, pp);
}

// round 15
// speedup vs baseline: 1.0003x; 1.0003x over previous
#include <cuda_runtime.h>
#include <cuda_bf16.h>
#include <math.h>

// Problem shape (fixed by the dataset): x = [4, 32, 4096, 128] fp32.
#define SEQ     4096
#define HDIM    128
#define HALF    (HDIM / 2)          // 64 rotation pairs per row
#define F4_ROW  (HDIM / 4)          // 32 float4 per row (2 pairs per float4)
#define BH      (4 * 32)            // 128 batch*head slices
#define SLICE   (SEQ * F4_ROW)      // float4 per bh-slice = 131072
#define SPLIT   2                   // bh-loop split -> 2x threads, 2x MLP
#define BH_PER  (BH / SPLIT)        // 64 bh iterations per thread
#define BATCH   8                   // loads in flight per thread

// ---------------------------------------------------------------------------
// Position loader with dtype sniffing (reference says int64; harness may have
// materialized int32/float32). Positions are small non-negative ints.
// ---------------------------------------------------------------------------
__device__ __forceinline__ double load_pos(const void* p, int s) {
    const unsigned int* w = (const unsigned int*)p;
    bool hi_zero = (w[1] == 0u) & (w[3] == 0u) & (w[5] == 0u) & (w[7] == 0u);
    bool lo_some = (w[0] | w[2] | w[4] | w[6]) != 0u;
    if (hi_zero && (lo_some || (w[8] | w[9]) == 0u)) {
        return (double)((const long long*)p)[s];
    }
    bool small_ints = (w[1] < (1u << 24)) & (w[2] < (1u << 24)) &
                      (w[3] < (1u << 24));
    if (small_ints) return (double)((const int*)p)[s];
    return (double)((const float*)p)[s];
}

__device__ __forceinline__ float reduce_2pi(double a) {
    const double INV_2PI = 0.15915494309189535;
    const double TWO_PI  = 6.283185307179586;
    double k = rint(a * INV_2PI);
    return (float)(a - k * TWO_PI);
}

// ---------------------------------------------------------------------------
// Fused kernel, best-measured configuration (R14 binary, resubmitted):
//   SPLIT=2, BATCH=8 prefetch-before-trig, 256 threads/CTA,
//   __ldg + plain stores, single runtime exp2 (second freq const-folded).
// ---------------------------------------------------------------------------
__global__ __launch_bounds__(256) void rope_fused(
    const float4* __restrict__ x, float4* __restrict__ out,
    const void* __restrict__ pos) {
    int t = blockIdx.x * blockDim.x + threadIdx.x;   // 0..SLICE-1
    int s = t >> 5;          // seq index
    int j = t & 31;          // float4 within row -> pairs 2j, 2j+1

    size_t off = (size_t)blockIdx.y * (size_t)BH_PER * SLICE + (size_t)t;

    // Prefetch batch 0 (independent of trig).
    float4 v[BATCH];
#pragma unroll
    for (int k = 0; k < BATCH; ++k)
        v[k] = __ldg(&x[off + (size_t)k * SLICE]);

    // Per-thread trig (hidden under the loads above). One runtime exp2:
    // f1/f0 ratio is a compile-time constant the compiler folds.
    double p = load_pos(pos, s);
    const double LOG2_THETA = 13.287712379549449;   // log2(10000)
    double f0 = exp2(-((double)(2 * j) / (double)HALF) * LOG2_THETA);
    double f1 = f0 * exp2(-(1.0 / (double)HALF) * LOG2_THETA); // const-folded
    float a0 = reduce_2pi(p * f0);
    float a1 = reduce_2pi(p * f1);
    float s0, c0, s1, c1;
    sincosf(a0, &s0, &c0);
    sincosf(a1, &s1, &c1);

#pragma unroll
    for (int bb = 0; bb < BH_PER / BATCH; ++bb) {
        // Rotate + store current batch.
#pragma unroll
        for (int k = 0; k < BATCH; ++k) {
            float4 r;
            r.x = c0 * v[k].x - s0 * v[k].y;
            r.y = s0 * v[k].x + c0 * v[k].y;
            r.z = c1 * v[k].z - s1 * v[k].w;
            r.w = s1 * v[k].z + c1 * v[k].w;
            out[off + (size_t)k * SLICE] = r;
        }
        off += (size_t)BATCH * SLICE;
        // Prefetch next batch.
        if (bb + 1 < BH_PER / BATCH) {
#pragma unroll
            for (int k = 0; k < BATCH; ++k)
                v[k] = __ldg(&x[off + (size_t)k * SLICE]);
        }
    }
}

// ---------------------------------------------------------------------------
// Entry point. Identify x vs token_positions by element count (robust to
// input ordering): x has 67108864 elements, positions 4096.
// ---------------------------------------------------------------------------
extern "C" void kernel_launch(void* const* d_in, const int* in_sizes, int n_in,
                              void* d_out, int out_size) {
    const void* xp = d_in[0];
    const void* pp = (n_in > 1) ? d_in[1] : d_in[0];
    if (n_in > 1 && in_sizes[0] < in_sizes[1]) {
        xp = d_in[1];
        pp = d_in[0];
    }
    const float4* x = (const float4*)xp;
    float4* out = (float4*)d_out;

    dim3 grid(SLICE / 256, SPLIT);
    rope_fused<<<grid, 256>>>(x, out, pp);
}

// round 17
// speedup vs baseline: 1.0160x; 1.0156x over previous
#include <cuda_runtime.h>
#include <cuda_bf16.h>
#include <math.h>

// Problem shape (fixed by the dataset): x = [4, 32, 4096, 128] fp32.
#define SEQ     4096
#define HDIM    128
#define HALF    (HDIM / 2)          // 64 rotation pairs per row
#define F4_ROW  (HDIM / 4)          // 32 float4 per row (2 pairs per float4)
#define BH      (4 * 32)            // 128 batch*head slices
#define SLICE   (SEQ * F4_ROW)      // float4 per bh-slice = 131072
#define SPLIT   2                   // bh-loop split -> 2x threads, 2x MLP
#define BH_PER  (BH / SPLIT)        // 64 bh iterations per thread
#define BATCH   8                   // loads in flight per thread

// ---------------------------------------------------------------------------
// Position loader with dtype sniffing (reference says int64; harness may have
// materialized int32/float32). Positions are small non-negative ints.
// ---------------------------------------------------------------------------
__device__ __forceinline__ double load_pos(const void* p, int s) {
    const unsigned int* w = (const unsigned int*)p;
    bool hi_zero = (w[1] == 0u) & (w[3] == 0u) & (w[5] == 0u) & (w[7] == 0u);
    bool lo_some = (w[0] | w[2] | w[4] | w[6]) != 0u;
    if (hi_zero && (lo_some || (w[8] | w[9]) == 0u)) {
        return (double)((const long long*)p)[s];
    }
    bool small_ints = (w[1] < (1u << 24)) & (w[2] < (1u << 24)) &
                      (w[3] < (1u << 24));
    if (small_ints) return (double)((const int*)p)[s];
    return (double)((const float*)p)[s];
}

__device__ __forceinline__ float reduce_2pi(double a) {
    const double INV_2PI = 0.15915494309189535;
    const double TWO_PI  = 6.283185307179586;
    double k = rint(a * INV_2PI);
    return (float)(a - k * TWO_PI);
}

// ---------------------------------------------------------------------------
// Fused kernel — best-TOTAL configuration (R7/R12 skeleton):
//   SPLIT=2, BATCH=8 prefetch-before-trig, 256 threads/CTA,
//   __ldcs loads + __stcs stores (evict-first: minimizes L2 thrash across
//   back-to-back graph replays in the timed loop),
//   single runtime exp2 (second freq const-folded).
// ---------------------------------------------------------------------------
__global__ __launch_bounds__(256) void rope_fused(
    const float4* __restrict__ x, float4* __restrict__ out,
    const void* __restrict__ pos) {
    int t = blockIdx.x * blockDim.x + threadIdx.x;   // 0..SLICE-1
    int s = t >> 5;          // seq index
    int j = t & 31;          // float4 within row -> pairs 2j, 2j+1

    size_t off = (size_t)blockIdx.y * (size_t)BH_PER * SLICE + (size_t)t;

    // Prefetch batch 0 (independent of trig).
    float4 v[BATCH];
#pragma unroll
    for (int k = 0; k < BATCH; ++k)
        v[k] = __ldcs(&x[off + (size_t)k * SLICE]);

    // Per-thread trig (hidden under the loads above). One runtime exp2:
    // f1/f0 ratio is a compile-time constant the compiler folds.
    double p = load_pos(pos, s);
    const double LOG2_THETA = 13.287712379549449;   // log2(10000)
    double f0 = exp2(-((double)(2 * j) / (double)HALF) * LOG2_THETA);
    double f1 = f0 * exp2(-(1.0 / (double)HALF) * LOG2_THETA); // const-folded
    float a0 = reduce_2pi(p * f0);
    float a1 = reduce_2pi(p * f1);
    float s0, c0, s1, c1;
    sincosf(a0, &s0, &c0);
    sincosf(a1, &s1, &c1);

#pragma unroll
    for (int bb = 0; bb < BH_PER / BATCH; ++bb) {
        // Rotate + store current batch.
#pragma unroll
        for (int k = 0; k < BATCH; ++k) {
            float4 r;
            r.x = c0 * v[k].x - s0 * v[k].y;
            r.y = s0 * v[k].x + c0 * v[k].y;
            r.z = c1 * v[k].z - s1 * v[k].w;
            r.w = s1 * v[k].z + c1 * v[k].w;
            __stcs(&out[off + (size_t)k * SLICE], r);
        }
        off += (size_t)BATCH * SLICE;
        // Prefetch next batch.
        if (bb + 1 < BH_PER / BATCH) {
#pragma unroll
            for (int k = 0; k < BATCH; ++k)
                v[k] = __ldcs(&x[off + (size_t)k * SLICE]);
        }
    }
}

// ---------------------------------------------------------------------------
// Entry point. Identify x vs token_positions by element count (robust to
// input ordering): x has 67108864 elements, positions 4096.
// ---------------------------------------------------------------------------
extern "C" void kernel_launch(void* const* d_in, const int* in_sizes, int n_in,
                              void* d_out, int out_size) {
    const void* xp = d_in[0];
    const void* pp = (n_in > 1) ? d_in[1] : d_in[0];
    if (n_in > 1 && in_sizes[0] < in_sizes[1]) {
        xp = d_in[1];
        pp = d_in[0];
    }
    const float4* x = (const float4*)xp;
    float4* out = (float4*)d_out;

    dim3 grid(SLICE / 256, SPLIT);
    rope_fused<<<grid, 256>>>(x, out, pp);
}